// round 1
// baseline (speedup 1.0000x reference)
#include <cuda_runtime.h>
#include <math.h>
#include <stdint.h>

// ---------------- constants ----------------
#define N_IMG    2
#define A_TOTAL  39375
#define PRE      2000
#define POST     300
#define SORT_N   65536

// output layout offsets (floats)
#define OFF_LOCS    0          // 2*39375*4 = 315000
#define OFF_SCORES  315000     // 2*39375*2 = 157500
#define OFF_ROIS    472500     // 600*4    = 2400
#define OFF_RIDX    474900     // 600
#define OFF_ANCH    475500     // 157500
// total 633000

// h (conv output, NHWC per level): lvl0 base 0 (2*100*100*256), lvl1 base 5120000, lvl2 base 6400000
__device__ float               g_h[6720000];
__device__ float               g_fg[N_IMG * A_TOTAL];
__device__ float               g_roi[N_IMG * A_TOTAL * 4];
__device__ unsigned long long  g_keys[N_IMG * SORT_N];
__device__ float               g_boxes[N_IMG * PRE * 4];
__device__ int                 g_valid[N_IMG * PRE];
__device__ unsigned long long  g_mask[N_IMG * PRE * 32];

// ---------------- conv 3x3 + bias + relu ----------------
// x: (2,256,H,W) NCHW.  out: g_h[hoff + (n*H*W + y*W + x)*256 + c]  (NHWC)
// block: 128 thr; tile: 64 oc x 32 px x 4 rows. grid: (ceil(W/32), ceil(H/4), 2*4)
__global__ __launch_bounds__(128, 4)
void conv3x3_relu(const float* __restrict__ x, const float* __restrict__ w,
                  const float* __restrict__ bias, int hoff, int H, int W) {
    __shared__ float s_in[8 * 6 * 36];     // [ic][row(6)][36]
    __shared__ float s_w[8 * 9 * 64];      // [(ic*9+k9)][oc]

    const int tid = threadIdx.x;
    const int tx  = tid & 7;     // px group: px = tx*4 + r
    const int ty  = tid >> 3;    // oc group: oc = ty*4 + q
    const int x0  = blockIdx.x * 32;
    const int y0  = blockIdx.y * 4;
    const int n   = blockIdx.z >> 2;
    const int oc0 = (blockIdx.z & 3) * 64;

    float acc[4][16];
#pragma unroll
    for (int a = 0; a < 4; a++)
#pragma unroll
        for (int b = 0; b < 16; b++) acc[a][b] = 0.f;

    const float* xn = x + (size_t)n * 256 * H * W;

    for (int ic0 = 0; ic0 < 256; ic0 += 8) {
        // weights: 64 oc x 8 ic x 9 = 1152 float4 loads
        for (int f = tid; f < 1152; f += 128) {
            int oc = f / 18;
            int kq = f % 18;
            const float4 v = *reinterpret_cast<const float4*>(
                w + (size_t)(oc0 + oc) * 2304 + ic0 * 9 + kq * 4);
            int k = kq * 4;
            s_w[(k + 0) * 64 + oc] = v.x;
            s_w[(k + 1) * 64 + oc] = v.y;
            s_w[(k + 2) * 64 + oc] = v.z;
            s_w[(k + 3) * 64 + oc] = v.w;
        }
        // input: 8 ic x 6 rows x 34 cols (zero padded to 36)
        for (int i = tid; i < 8 * 6 * 36; i += 128) {
            int ic  = i / 216;
            int rem = i % 216;
            int ry  = rem / 36;
            int xx  = rem % 36;
            float v = 0.f;
            int gy = y0 + ry - 1;
            int gx = x0 + xx - 1;
            if (xx < 34 && gy >= 0 && gy < H && gx >= 0 && gx < W)
                v = xn[(size_t)(ic0 + ic) * H * W + gy * W + gx];
            s_in[i] = v;
        }
        __syncthreads();

        for (int ic = 0; ic < 8; ic++) {
#pragma unroll
            for (int ky = 0; ky < 3; ky++) {
                float wv[3][4];
#pragma unroll
                for (int kx = 0; kx < 3; kx++) {
                    float4 w4 = *reinterpret_cast<const float4*>(
                        &s_w[(ic * 9 + ky * 3 + kx) * 64 + ty * 4]);
                    wv[kx][0] = w4.x; wv[kx][1] = w4.y; wv[kx][2] = w4.z; wv[kx][3] = w4.w;
                }
#pragma unroll
                for (int yy = 0; yy < 4; yy++) {
                    const float* row = &s_in[ic * 216 + (yy + ky) * 36 + tx * 4];
                    float in6[6];
                    float4 a4 = *reinterpret_cast<const float4*>(row);
                    float2 a2 = *reinterpret_cast<const float2*>(row + 4);
                    in6[0] = a4.x; in6[1] = a4.y; in6[2] = a4.z; in6[3] = a4.w;
                    in6[4] = a2.x; in6[5] = a2.y;
#pragma unroll
                    for (int kx = 0; kx < 3; kx++)
#pragma unroll
                        for (int q = 0; q < 4; q++)
#pragma unroll
                            for (int r = 0; r < 4; r++)
                                acc[yy][q * 4 + r] = fmaf(wv[kx][q], in6[r + kx], acc[yy][q * 4 + r]);
                }
            }
        }
        __syncthreads();
    }

    float bv[4];
#pragma unroll
    for (int q = 0; q < 4; q++) bv[q] = bias[oc0 + ty * 4 + q];

#pragma unroll
    for (int yy = 0; yy < 4; yy++) {
        int gy = y0 + yy;
        if (gy >= H) continue;
#pragma unroll
        for (int r = 0; r < 4; r++) {
            int gx = x0 + tx * 4 + r;
            if (gx >= W) continue;
            float* dst = g_h + hoff + ((size_t)(n * H * W) + (size_t)gy * W + gx) * 256 + oc0 + ty * 4;
            float4 o;
            o.x = fmaxf(acc[yy][0 * 4 + r] + bv[0], 0.f);
            o.y = fmaxf(acc[yy][1 * 4 + r] + bv[1], 0.f);
            o.z = fmaxf(acc[yy][2 * 4 + r] + bv[2], 0.f);
            o.w = fmaxf(acc[yy][3 * 4 + r] + bv[3], 0.f);
            *reinterpret_cast<float4*>(dst) = o;
        }
    }
}

// ---------------- heads: 18x256 projections + softmax fg ----------------
// warp per spatial position; 26250 positions total (2 images x 13125)
__global__ __launch_bounds__(256)
void heads_kernel(const float* __restrict__ score_w, const float* __restrict__ score_b,
                  const float* __restrict__ loc_w, const float* __restrict__ loc_b,
                  float* __restrict__ out) {
    __shared__ float s_w[18 * 256];
    __shared__ float s_b[18];
    int tid = threadIdx.x;
    for (int i = tid; i < 6 * 256; i += 256)  s_w[i] = score_w[i];
    for (int i = tid; i < 12 * 256; i += 256) s_w[6 * 256 + i] = loc_w[i];
    if (tid < 6)       s_b[tid] = score_b[tid];
    else if (tid < 18) s_b[tid] = loc_b[tid - 6];
    __syncthreads();

    int warp = tid >> 5, lane = tid & 31;
    int P = blockIdx.x * 8 + warp;
    if (P >= 26250) return;
    int n = P / 13125;
    int p = P % 13125;
    int aoff, hbase, ploc;
    if (p < 10000)      { ploc = p;         aoff = 0;     hbase = n * 2560000 + ploc * 256; }
    else if (p < 12500) { ploc = p - 10000; aoff = 30000; hbase = 5120000 + n * 640000 + ploc * 256; }
    else                { ploc = p - 12500; aoff = 37500; hbase = 6400000 + n * 160000 + ploc * 256; }

    const float4* hp = reinterpret_cast<const float4*>(&g_h[hbase]);
    float4 v0 = hp[lane];
    float4 v1 = hp[lane + 32];
    float hv[8] = {v0.x, v0.y, v0.z, v0.w, v1.x, v1.y, v1.z, v1.w};

    float res[18];
#pragma unroll
    for (int o = 0; o < 18; o++) {
        const float* wr = &s_w[o * 256];
        float4 wa = *reinterpret_cast<const float4*>(&wr[lane * 4]);
        float4 wb = *reinterpret_cast<const float4*>(&wr[128 + lane * 4]);
        float s = hv[0] * wa.x + hv[1] * wa.y + hv[2] * wa.z + hv[3] * wa.w +
                  hv[4] * wb.x + hv[5] * wb.y + hv[6] * wb.z + hv[7] * wb.w;
#pragma unroll
        for (int off = 16; off; off >>= 1) s += __shfl_xor_sync(0xffffffffu, s, off);
        res[o] = s + s_b[o];
    }

    if (lane == 0) {
        int aid0 = aoff + ploc * 3;
#pragma unroll
        for (int a = 0; a < 3; a++) {
            int aid = aid0 + a;
            float s0 = res[a * 2 + 0], s1 = res[a * 2 + 1];
            out[OFF_SCORES + (size_t)(n * A_TOTAL + aid) * 2 + 0] = s0;
            out[OFF_SCORES + (size_t)(n * A_TOTAL + aid) * 2 + 1] = s1;
            g_fg[n * A_TOTAL + aid] = 1.f / (1.f + expf(s0 - s1));
#pragma unroll
            for (int c = 0; c < 4; c++)
                out[OFF_LOCS + (size_t)(n * A_TOTAL + aid) * 4 + c] = res[6 + a * 4 + c];
        }
    }
}

// ---------------- propose: loc2bbox + clip + valid + sort key ----------------
__device__ __forceinline__ unsigned int flip_f(float f) {
    unsigned int b = __float_as_uint(f);
    return (b & 0x80000000u) ? ~b : (b | 0x80000000u);
}

__global__ void propose_kernel(const float* __restrict__ anchors, const float* __restrict__ out) {
    int t = blockIdx.x * 256 + threadIdx.x;
    if (t >= N_IMG * SORT_N) return;
    int n = t / SORT_N, s = t % SORT_N;
    unsigned long long key = ~0ull;
    if (s < A_TOTAL) {
        float4 lc = *reinterpret_cast<const float4*>(out + OFF_LOCS + (size_t)(n * A_TOTAL + s) * 4);
        float4 an = *reinterpret_cast<const float4*>(anchors + (size_t)s * 4);
        float sh = an.z - an.x, sw = an.w - an.y;
        float cy = an.x + 0.5f * sh, cx = an.y + 0.5f * sw;
        float ncy = lc.x * sh + cy, ncx = lc.y * sw + cx;
        float nh = expf(lc.z) * sh, nw = expf(lc.w) * sw;
        float y1 = fminf(fmaxf(ncy - 0.5f * nh, 0.f), 800.f);
        float x1 = fminf(fmaxf(ncx - 0.5f * nw, 0.f), 800.f);
        float y2 = fminf(fmaxf(ncy + 0.5f * nh, 0.f), 800.f);
        float x2 = fminf(fmaxf(ncx + 0.5f * nw, 0.f), 800.f);
        float4 r = make_float4(y1, x1, y2, x2);
        *reinterpret_cast<float4*>(&g_roi[(size_t)(n * A_TOTAL + s) * 4]) = r;
        bool valid = ((y2 - y1) >= 16.f) && ((x2 - x1) >= 16.f);
        float sc = valid ? g_fg[n * A_TOTAL + s] : -INFINITY;
        unsigned int u = flip_f(sc);
        key = ((unsigned long long)(~u) << 32) | (unsigned int)s;
    }
    g_keys[t] = key;
}

// ---------------- bitonic sort of 2 x 65536 u64 keys (ascending) ----------------
__global__ __launch_bounds__(1024) void bitonic_shared_a() {
    __shared__ unsigned long long sm[2048];
    int base = blockIdx.x * 2048;
    int tid = threadIdx.x;
    sm[tid] = g_keys[base + tid];
    sm[tid + 1024] = g_keys[base + tid + 1024];
    __syncthreads();
    for (int k = 2; k <= 2048; k <<= 1) {
        for (int j = k >> 1; j > 0; j >>= 1) {
            int i1 = ((tid / j) * 2 * j) + (tid % j);
            int i2 = i1 + j;
            bool dir = ((((base + i1) & 65535) & k) == 0);
            unsigned long long a = sm[i1], b = sm[i2];
            if (dir ? (a > b) : (a < b)) { sm[i1] = b; sm[i2] = a; }
            __syncthreads();
        }
    }
    g_keys[base + tid] = sm[tid];
    g_keys[base + tid + 1024] = sm[tid + 1024];
}

__global__ void bitonic_global(int j, int k) {
    int t = blockIdx.x * 256 + threadIdx.x;   // 65536 threads
    int i1 = ((t / j) * 2 * j) + (t % j);
    int i2 = i1 + j;
    bool dir = (((i1 & 65535) & k) == 0);
    unsigned long long a = g_keys[i1], b = g_keys[i2];
    if (dir ? (a > b) : (a < b)) { g_keys[i1] = b; g_keys[i2] = a; }
}

__global__ __launch_bounds__(1024) void bitonic_shared_b(int k) {
    __shared__ unsigned long long sm[2048];
    int base = blockIdx.x * 2048;
    int tid = threadIdx.x;
    sm[tid] = g_keys[base + tid];
    sm[tid + 1024] = g_keys[base + tid + 1024];
    __syncthreads();
    bool dir = (((base & 65535) & k) == 0);
    for (int j = 1024; j > 0; j >>= 1) {
        int i1 = ((tid / j) * 2 * j) + (tid % j);
        int i2 = i1 + j;
        unsigned long long a = sm[i1], b = sm[i2];
        if (dir ? (a > b) : (a < b)) { sm[i1] = b; sm[i2] = a; }
        __syncthreads();
    }
    g_keys[base + tid] = sm[tid];
    g_keys[base + tid + 1024] = sm[tid + 1024];
}

// ---------------- gather top-2000 boxes ----------------
__global__ void gather_topk() {
    int t = blockIdx.x * 256 + threadIdx.x;
    if (t >= N_IMG * PRE) return;
    int n = t / PRE, r = t % PRE;
    unsigned long long key = g_keys[(size_t)n * SORT_N + r];
    unsigned int hi = (unsigned int)(key >> 32);
    int valid = hi < 0xFF800000u;
    unsigned int idx = (unsigned int)key;
    float4 bx = make_float4(0.f, 0.f, 0.f, 0.f);
    if (idx < A_TOTAL)
        bx = *reinterpret_cast<const float4*>(&g_roi[(size_t)(n * A_TOTAL + idx) * 4]);
    *reinterpret_cast<float4*>(&g_boxes[(size_t)t * 4]) = bx;
    g_valid[t] = valid;
}

// ---------------- NMS suppression bitmask ----------------
__global__ void nms_mask() {
    int t = blockIdx.x * 256 + threadIdx.x;
    int n = blockIdx.y;
    if (t >= PRE * 32) return;
    int i = t >> 5, w = t & 31;
    const float4 bi = *reinterpret_cast<const float4*>(&g_boxes[(size_t)(n * PRE + i) * 4]);
    float area_i = (bi.z - bi.x) * (bi.w - bi.y);
    unsigned long long m = 0ull;
    int j0 = w * 64;
    for (int b = 0; b < 64; b++) {
        int j = j0 + b;
        if (j <= i || j >= PRE) continue;
        float4 bj = *reinterpret_cast<const float4*>(&g_boxes[(size_t)(n * PRE + j) * 4]);
        float ty = fmaxf(bi.x, bj.x), txx = fmaxf(bi.y, bj.y);
        float by = fminf(bi.z, bj.z), bxx = fminf(bi.w, bj.w);
        float hh = fmaxf(by - ty, 0.f), ww = fmaxf(bxx - txx, 0.f);
        float inter = hh * ww;
        float area_j = (bj.z - bj.x) * (bj.w - bj.y);
        float iou = inter / (area_i + area_j - inter + 1e-12f);
        if (iou > 0.7f) m |= (1ull << b);
    }
    g_mask[((size_t)n * PRE + i) * 32 + w] = m;
}

// ---------------- greedy NMS reduce + emit rois / roi_indices ----------------
__global__ void nms_finalize(float* __restrict__ out) {
    int n = blockIdx.x;
    int tid = threadIdx.x;
    __shared__ unsigned long long sup_sh[32];

    for (int i = tid; i < POST * 4; i += 256) out[OFF_ROIS + (size_t)n * POST * 4 + i] = 0.f;
    for (int i = tid; i < POST; i += 256)     out[OFF_RIDX + (size_t)n * POST + i] = (float)n;
    __syncthreads();

    if (tid < 32) {
        unsigned long long sup = 0ull;
        for (int b = 0; b < 64; b++) {
            int i = tid * 64 + b;
            if (i >= PRE || !g_valid[n * PRE + i]) sup |= (1ull << b);
        }
        const unsigned long long* mrow = &g_mask[(size_t)n * PRE * 32];
        for (int i = 0; i < PRE; i++) {
            unsigned long long mi = mrow[(size_t)i * 32 + tid];
            unsigned long long owner = __shfl_sync(0xffffffffu, sup, i >> 6);
            bool alive = ((owner >> (i & 63)) & 1ull) == 0ull;
            if (alive) sup |= mi;
        }
        sup_sh[tid] = sup;
    }
    __syncthreads();

    if (tid == 0) {
        int k = 0;
        for (int i = 0; i < PRE && k < POST; i++) {
            if (!((sup_sh[i >> 6] >> (i & 63)) & 1ull)) {
                const float4 bx = *reinterpret_cast<const float4*>(&g_boxes[(size_t)(n * PRE + i) * 4]);
                float* dst = out + OFF_ROIS + (size_t)(n * POST + k) * 4;
                dst[0] = bx.x; dst[1] = bx.y; dst[2] = bx.z; dst[3] = bx.w;
                k++;
            }
        }
    }
}

// ---------------- launch ----------------
extern "C" void kernel_launch(void* const* d_in, const int* in_sizes, int n_in,
                              void* d_out, int out_size) {
    const float* feat0   = (const float*)d_in[0];
    const float* feat1   = (const float*)d_in[1];
    const float* feat2   = (const float*)d_in[2];
    const float* conv_w  = (const float*)d_in[3];
    const float* conv_b  = (const float*)d_in[4];
    const float* score_w = (const float*)d_in[5];
    const float* score_b = (const float*)d_in[6];
    const float* loc_w   = (const float*)d_in[7];
    const float* loc_b   = (const float*)d_in[8];
    const float* anchors = (const float*)d_in[9];
    float* out = (float*)d_out;

    // conv 3x3 per level  (hoff, H, W)
    conv3x3_relu<<<dim3(4, 25, 8), 128>>>(feat0, conv_w, conv_b, 0,       100, 100);
    conv3x3_relu<<<dim3(2, 13, 8), 128>>>(feat1, conv_w, conv_b, 5120000, 50, 50);
    conv3x3_relu<<<dim3(1,  7, 8), 128>>>(feat2, conv_w, conv_b, 6400000, 25, 25);

    // heads: 26250 positions, 8 warps/block
    heads_kernel<<<3282, 256>>>(score_w, score_b, loc_w, loc_b, out);

    // proposals + sort keys (2 x 65536)
    propose_kernel<<<512, 256>>>(anchors, out);

    // bitonic sort ascending per 65536 segment
    bitonic_shared_a<<<64, 1024>>>();
    for (int k = 4096; k <= 65536; k <<= 1) {
        for (int j = k >> 1; j >= 2048; j >>= 1)
            bitonic_global<<<256, 256>>>(j, k);
        bitonic_shared_b<<<64, 1024>>>(k);
    }

    // top-2000 gather, NMS mask, finalize
    gather_topk<<<16, 256>>>();
    nms_mask<<<dim3(250, 2), 256>>>();
    nms_finalize<<<2, 256>>>(out);

    // anchors passthrough
    cudaMemcpyAsync(out + OFF_ANCH, anchors, (size_t)A_TOTAL * 4 * sizeof(float),
                    cudaMemcpyDeviceToDevice, 0);
}

// round 2
// speedup vs baseline: 1.2807x; 1.2807x over previous
#include <cuda_runtime.h>
#include <math.h>
#include <stdint.h>

// ---------------- constants ----------------
#define N_IMG    2
#define A_TOTAL  39375
#define PRE      2000
#define POST     300
#define SORT_N   65536

// output layout offsets (floats)
#define OFF_LOCS    0          // 2*39375*4 = 315000
#define OFF_SCORES  315000     // 2*39375*2 = 157500
#define OFF_ROIS    472500     // 600*4    = 2400
#define OFF_RIDX    474900     // 600
#define OFF_ANCH    475500     // 157500
// total 633000

// h (conv output, NHWC per level): lvl0 base 0 (2*100*100*256), lvl1 base 5120000, lvl2 base 6400000
__device__ float               g_h[6720000];
__device__ float               g_fg[N_IMG * A_TOTAL];
__device__ float               g_roi[N_IMG * A_TOTAL * 4];
__device__ unsigned long long  g_keys[N_IMG * SORT_N];
__device__ float               g_boxes[N_IMG * PRE * 4];
__device__ int                 g_valid[N_IMG * PRE];
__device__ unsigned long long  g_mask[N_IMG * PRE * 32];

// ---------------- packed f32x2 helpers ----------------
#define PACK2(d, lo, hi) \
    asm("mov.b64 %0, {%1, %2};" : "=l"(d) : "r"(__float_as_uint(lo)), "r"(__float_as_uint(hi)))
#define FMA2(d, a, b) \
    asm("fma.rn.f32x2 %0, %1, %2, %0;" : "+l"(d) : "l"(a), "l"(b))
#define UNPACK2(lo, hi, v) \
    do { unsigned int _ulo, _uhi; \
         asm("mov.b64 {%0, %1}, %2;" : "=r"(_ulo), "=r"(_uhi) : "l"(v)); \
         lo = __uint_as_float(_ulo); hi = __uint_as_float(_uhi); } while (0)

// ---------------- conv 3x3 + bias + relu (all 3 levels, one launch) ----------------
// x: (2,256,H,W) NCHW.  out: g_h[hoff + (n*H*W + y*W + x)*256 + c]  (NHWC)
// block: 128 thr; tile: 64 oc x 32 px x 4 rows.
// grid.x = 800 (lvl0: 4x25x8) + 208 (lvl1: 2x13x8) + 56 (lvl2: 1x7x8) = 1064
__global__ __launch_bounds__(128, 4)
void conv3x3_relu_all(const float* __restrict__ f0, const float* __restrict__ f1,
                      const float* __restrict__ f2, const float* __restrict__ w,
                      const float* __restrict__ bias) {
    __shared__ float s_in[8 * 6 * 36];     // [ic][row(6)][36]
    __shared__ float s_w[8 * 9 * 64];      // [(ic*9+k9)][oc]

    // decode block -> (level, bx, by, bz)
    int b = blockIdx.x;
    const float* x;
    int hoff, H, W, bx, by, bz;
    if (b < 800) {
        x = f0; hoff = 0; H = 100; W = 100;
        bx = b & 3; by = (b >> 2) % 25; bz = b / 100;
    } else if (b < 1008) {
        int l = b - 800;
        x = f1; hoff = 5120000; H = 50; W = 50;
        bx = l & 1; by = (l >> 1) % 13; bz = l / 26;
    } else {
        int l = b - 1008;
        x = f2; hoff = 6400000; H = 25; W = 25;
        bx = 0; by = l % 7; bz = l / 7;
    }

    const int tid = threadIdx.x;
    const int tx  = tid & 7;     // px group: px = tx*4 + r
    const int ty  = tid >> 3;    // oc group: oc = ty*4 + q
    const int x0  = bx * 32;
    const int y0  = by * 4;
    const int n   = bz >> 2;
    const int oc0 = (bz & 3) * 64;

    // packed accumulators: [yy][q*2 + rp], rp=0 -> (r0,r1), rp=1 -> (r2,r3)
    unsigned long long acc2[4][8];
#pragma unroll
    for (int a = 0; a < 4; a++)
#pragma unroll
        for (int c = 0; c < 8; c++) acc2[a][c] = 0ull;

    const float* xn = x + (size_t)n * 256 * H * W;

    for (int ic0 = 0; ic0 < 256; ic0 += 8) {
        // weights: 64 oc x 8 ic x 9 = 1152 float4 loads
        for (int f = tid; f < 1152; f += 128) {
            int oc = f / 18;
            int kq = f % 18;
            const float4 v = *reinterpret_cast<const float4*>(
                w + (size_t)(oc0 + oc) * 2304 + ic0 * 9 + kq * 4);
            int k = kq * 4;
            s_w[(k + 0) * 64 + oc] = v.x;
            s_w[(k + 1) * 64 + oc] = v.y;
            s_w[(k + 2) * 64 + oc] = v.z;
            s_w[(k + 3) * 64 + oc] = v.w;
        }
        // input: 8 ic x 6 rows x 34 cols (zero padded to 36)
        for (int i = tid; i < 8 * 6 * 36; i += 128) {
            int ic  = i / 216;
            int rem = i % 216;
            int ry  = rem / 36;
            int xx  = rem % 36;
            float v = 0.f;
            int gy = y0 + ry - 1;
            int gx = x0 + xx - 1;
            if (xx < 34 && gy >= 0 && gy < H && gx >= 0 && gx < W)
                v = xn[(size_t)(ic0 + ic) * H * W + gy * W + gx];
            s_in[i] = v;
        }
        __syncthreads();

        for (int ic = 0; ic < 8; ic++) {
#pragma unroll
            for (int ky = 0; ky < 3; ky++) {
                // duplicated weight pairs: wp[kx][q] = (w, w)
                unsigned long long wp[3][4];
#pragma unroll
                for (int kx = 0; kx < 3; kx++) {
                    float4 w4 = *reinterpret_cast<const float4*>(
                        &s_w[(ic * 9 + ky * 3 + kx) * 64 + ty * 4]);
                    PACK2(wp[kx][0], w4.x, w4.x);
                    PACK2(wp[kx][1], w4.y, w4.y);
                    PACK2(wp[kx][2], w4.z, w4.z);
                    PACK2(wp[kx][3], w4.w, w4.w);
                }
#pragma unroll
                for (int yy = 0; yy < 4; yy++) {
                    const float* row = &s_in[ic * 216 + (yy + ky) * 36 + tx * 4];
                    float4 a4 = *reinterpret_cast<const float4*>(row);
                    float2 a2 = *reinterpret_cast<const float2*>(row + 4);
                    // sliding input pairs p[k] = (in[k], in[k+1])
                    unsigned long long p[5];
                    PACK2(p[0], a4.x, a4.y);
                    PACK2(p[1], a4.y, a4.z);
                    PACK2(p[2], a4.z, a4.w);
                    PACK2(p[3], a4.w, a2.x);
                    PACK2(p[4], a2.x, a2.y);
#pragma unroll
                    for (int kx = 0; kx < 3; kx++) {
#pragma unroll
                        for (int q = 0; q < 4; q++) {
                            FMA2(acc2[yy][q * 2 + 0], wp[kx][q], p[kx]);
                            FMA2(acc2[yy][q * 2 + 1], wp[kx][q], p[kx + 2]);
                        }
                    }
                }
            }
        }
        __syncthreads();
    }

    float bv[4];
#pragma unroll
    for (int q = 0; q < 4; q++) bv[q] = bias[oc0 + ty * 4 + q];

#pragma unroll
    for (int yy = 0; yy < 4; yy++) {
        int gy = y0 + yy;
        if (gy >= H) continue;
        float a[4][4];   // [q][r]
#pragma unroll
        for (int q = 0; q < 4; q++) {
            UNPACK2(a[q][0], a[q][1], acc2[yy][q * 2 + 0]);
            UNPACK2(a[q][2], a[q][3], acc2[yy][q * 2 + 1]);
        }
#pragma unroll
        for (int r = 0; r < 4; r++) {
            int gx = x0 + tx * 4 + r;
            if (gx >= W) continue;
            float* dst = g_h + hoff + ((size_t)(n * H * W) + (size_t)gy * W + gx) * 256 + oc0 + ty * 4;
            float4 o;
            o.x = fmaxf(a[0][r] + bv[0], 0.f);
            o.y = fmaxf(a[1][r] + bv[1], 0.f);
            o.z = fmaxf(a[2][r] + bv[2], 0.f);
            o.w = fmaxf(a[3][r] + bv[3], 0.f);
            *reinterpret_cast<float4*>(dst) = o;
        }
    }
}

// ---------------- heads: 18x256 projections + softmax fg ----------------
// warp per spatial position; 26250 positions total (2 images x 13125)
__global__ __launch_bounds__(256)
void heads_kernel(const float* __restrict__ score_w, const float* __restrict__ score_b,
                  const float* __restrict__ loc_w, const float* __restrict__ loc_b,
                  float* __restrict__ out) {
    __shared__ float s_w[18 * 256];
    __shared__ float s_b[18];
    int tid = threadIdx.x;
    for (int i = tid; i < 6 * 256; i += 256)  s_w[i] = score_w[i];
    for (int i = tid; i < 12 * 256; i += 256) s_w[6 * 256 + i] = loc_w[i];
    if (tid < 6)       s_b[tid] = score_b[tid];
    else if (tid < 18) s_b[tid] = loc_b[tid - 6];
    __syncthreads();

    int warp = tid >> 5, lane = tid & 31;
    int P = blockIdx.x * 8 + warp;
    if (P >= 26250) return;
    int n = P / 13125;
    int p = P % 13125;
    int aoff, hbase, ploc;
    if (p < 10000)      { ploc = p;         aoff = 0;     hbase = n * 2560000 + ploc * 256; }
    else if (p < 12500) { ploc = p - 10000; aoff = 30000; hbase = 5120000 + n * 640000 + ploc * 256; }
    else                { ploc = p - 12500; aoff = 37500; hbase = 6400000 + n * 160000 + ploc * 256; }

    const float4* hp = reinterpret_cast<const float4*>(&g_h[hbase]);
    float4 v0 = hp[lane];
    float4 v1 = hp[lane + 32];
    float hv[8] = {v0.x, v0.y, v0.z, v0.w, v1.x, v1.y, v1.z, v1.w};

    float res[18];
#pragma unroll
    for (int o = 0; o < 18; o++) {
        const float* wr = &s_w[o * 256];
        float4 wa = *reinterpret_cast<const float4*>(&wr[lane * 4]);
        float4 wb = *reinterpret_cast<const float4*>(&wr[128 + lane * 4]);
        float s = hv[0] * wa.x + hv[1] * wa.y + hv[2] * wa.z + hv[3] * wa.w +
                  hv[4] * wb.x + hv[5] * wb.y + hv[6] * wb.z + hv[7] * wb.w;
#pragma unroll
        for (int off = 16; off; off >>= 1) s += __shfl_xor_sync(0xffffffffu, s, off);
        res[o] = s + s_b[o];
    }

    if (lane == 0) {
        int aid0 = aoff + ploc * 3;
#pragma unroll
        for (int a = 0; a < 3; a++) {
            int aid = aid0 + a;
            float s0 = res[a * 2 + 0], s1 = res[a * 2 + 1];
            out[OFF_SCORES + (size_t)(n * A_TOTAL + aid) * 2 + 0] = s0;
            out[OFF_SCORES + (size_t)(n * A_TOTAL + aid) * 2 + 1] = s1;
            g_fg[n * A_TOTAL + aid] = 1.f / (1.f + expf(s0 - s1));
#pragma unroll
            for (int c = 0; c < 4; c++)
                out[OFF_LOCS + (size_t)(n * A_TOTAL + aid) * 4 + c] = res[6 + a * 4 + c];
        }
    }
}

// ---------------- propose: loc2bbox + clip + valid + sort key ----------------
__device__ __forceinline__ unsigned int flip_f(float f) {
    unsigned int b = __float_as_uint(f);
    return (b & 0x80000000u) ? ~b : (b | 0x80000000u);
}

__global__ void propose_kernel(const float* __restrict__ anchors, const float* __restrict__ out) {
    int t = blockIdx.x * 256 + threadIdx.x;
    if (t >= N_IMG * SORT_N) return;
    int n = t / SORT_N, s = t % SORT_N;
    unsigned long long key = ~0ull;
    if (s < A_TOTAL) {
        float4 lc = *reinterpret_cast<const float4*>(out + OFF_LOCS + (size_t)(n * A_TOTAL + s) * 4);
        float4 an = *reinterpret_cast<const float4*>(anchors + (size_t)s * 4);
        float sh = an.z - an.x, sw = an.w - an.y;
        float cy = an.x + 0.5f * sh, cx = an.y + 0.5f * sw;
        float ncy = lc.x * sh + cy, ncx = lc.y * sw + cx;
        float nh = expf(lc.z) * sh, nw = expf(lc.w) * sw;
        float y1 = fminf(fmaxf(ncy - 0.5f * nh, 0.f), 800.f);
        float x1 = fminf(fmaxf(ncx - 0.5f * nw, 0.f), 800.f);
        float y2 = fminf(fmaxf(ncy + 0.5f * nh, 0.f), 800.f);
        float x2 = fminf(fmaxf(ncx + 0.5f * nw, 0.f), 800.f);
        float4 r = make_float4(y1, x1, y2, x2);
        *reinterpret_cast<float4*>(&g_roi[(size_t)(n * A_TOTAL + s) * 4]) = r;
        bool valid = ((y2 - y1) >= 16.f) && ((x2 - x1) >= 16.f);
        float sc = valid ? g_fg[n * A_TOTAL + s] : -INFINITY;
        unsigned int u = flip_f(sc);
        key = ((unsigned long long)(~u) << 32) | (unsigned int)s;
    }
    g_keys[t] = key;
}

// ---------------- bitonic sort of 2 x 65536 u64 keys (ascending) ----------------
__global__ __launch_bounds__(1024) void bitonic_shared_a() {
    __shared__ unsigned long long sm[2048];
    int base = blockIdx.x * 2048;
    int tid = threadIdx.x;
    sm[tid] = g_keys[base + tid];
    sm[tid + 1024] = g_keys[base + tid + 1024];
    __syncthreads();
    for (int k = 2; k <= 2048; k <<= 1) {
        for (int j = k >> 1; j > 0; j >>= 1) {
            int i1 = ((tid / j) * 2 * j) + (tid % j);
            int i2 = i1 + j;
            bool dir = ((((base + i1) & 65535) & k) == 0);
            unsigned long long a = sm[i1], b = sm[i2];
            if (dir ? (a > b) : (a < b)) { sm[i1] = b; sm[i2] = a; }
            __syncthreads();
        }
    }
    g_keys[base + tid] = sm[tid];
    g_keys[base + tid + 1024] = sm[tid + 1024];
}

__global__ void bitonic_global(int j, int k) {
    int t = blockIdx.x * 256 + threadIdx.x;   // 65536 threads
    int i1 = ((t / j) * 2 * j) + (t % j);
    int i2 = i1 + j;
    bool dir = (((i1 & 65535) & k) == 0);
    unsigned long long a = g_keys[i1], b = g_keys[i2];
    if (dir ? (a > b) : (a < b)) { g_keys[i1] = b; g_keys[i2] = a; }
}

__global__ __launch_bounds__(1024) void bitonic_shared_b(int k) {
    __shared__ unsigned long long sm[2048];
    int base = blockIdx.x * 2048;
    int tid = threadIdx.x;
    sm[tid] = g_keys[base + tid];
    sm[tid + 1024] = g_keys[base + tid + 1024];
    __syncthreads();
    bool dir = (((base & 65535) & k) == 0);
    for (int j = 1024; j > 0; j >>= 1) {
        int i1 = ((tid / j) * 2 * j) + (tid % j);
        int i2 = i1 + j;
        unsigned long long a = sm[i1], b = sm[i2];
        if (dir ? (a > b) : (a < b)) { sm[i1] = b; sm[i2] = a; }
        __syncthreads();
    }
    g_keys[base + tid] = sm[tid];
    g_keys[base + tid + 1024] = sm[tid + 1024];
}

// ---------------- gather top-2000 boxes ----------------
__global__ void gather_topk() {
    int t = blockIdx.x * 256 + threadIdx.x;
    if (t >= N_IMG * PRE) return;
    int n = t / PRE, r = t % PRE;
    unsigned long long key = g_keys[(size_t)n * SORT_N + r];
    unsigned int hi = (unsigned int)(key >> 32);
    int valid = hi < 0xFF800000u;
    unsigned int idx = (unsigned int)key;
    float4 bx = make_float4(0.f, 0.f, 0.f, 0.f);
    if (idx < A_TOTAL)
        bx = *reinterpret_cast<const float4*>(&g_roi[(size_t)(n * A_TOTAL + idx) * 4]);
    *reinterpret_cast<float4*>(&g_boxes[(size_t)t * 4]) = bx;
    g_valid[t] = valid;
}

// ---------------- NMS suppression bitmask ----------------
__global__ void nms_mask() {
    int t = blockIdx.x * 256 + threadIdx.x;
    int n = blockIdx.y;
    if (t >= PRE * 32) return;
    int i = t >> 5, w = t & 31;
    const float4 bi = *reinterpret_cast<const float4*>(&g_boxes[(size_t)(n * PRE + i) * 4]);
    float area_i = (bi.z - bi.x) * (bi.w - bi.y);
    unsigned long long m = 0ull;
    int j0 = w * 64;
    for (int b = 0; b < 64; b++) {
        int j = j0 + b;
        if (j <= i || j >= PRE) continue;
        float4 bj = *reinterpret_cast<const float4*>(&g_boxes[(size_t)(n * PRE + j) * 4]);
        float ty = fmaxf(bi.x, bj.x), txx = fmaxf(bi.y, bj.y);
        float by = fminf(bi.z, bj.z), bxx = fminf(bi.w, bj.w);
        float hh = fmaxf(by - ty, 0.f), ww = fmaxf(bxx - txx, 0.f);
        float inter = hh * ww;
        float area_j = (bj.z - bj.x) * (bj.w - bj.y);
        float iou = inter / (area_i + area_j - inter + 1e-12f);
        if (iou > 0.7f) m |= (1ull << b);
    }
    g_mask[((size_t)n * PRE + i) * 32 + w] = m;
}

// ---------------- greedy NMS reduce + emit rois / roi_indices ----------------
__global__ void nms_finalize(float* __restrict__ out) {
    int n = blockIdx.x;
    int tid = threadIdx.x;
    __shared__ unsigned long long sup_sh[32];

    for (int i = tid; i < POST * 4; i += 256) out[OFF_ROIS + (size_t)n * POST * 4 + i] = 0.f;
    for (int i = tid; i < POST; i += 256)     out[OFF_RIDX + (size_t)n * POST + i] = (float)n;
    __syncthreads();

    if (tid < 32) {
        unsigned long long sup = 0ull;
        for (int b = 0; b < 64; b++) {
            int i = tid * 64 + b;
            if (i >= PRE || !g_valid[n * PRE + i]) sup |= (1ull << b);
        }
        const unsigned long long* mrow = &g_mask[(size_t)n * PRE * 32];
        for (int i = 0; i < PRE; i++) {
            unsigned long long mi = mrow[(size_t)i * 32 + tid];
            unsigned long long owner = __shfl_sync(0xffffffffu, sup, i >> 6);
            bool alive = ((owner >> (i & 63)) & 1ull) == 0ull;
            if (alive) sup |= mi;
        }
        sup_sh[tid] = sup;
    }
    __syncthreads();

    if (tid == 0) {
        int k = 0;
        for (int i = 0; i < PRE && k < POST; i++) {
            if (!((sup_sh[i >> 6] >> (i & 63)) & 1ull)) {
                const float4 bx = *reinterpret_cast<const float4*>(&g_boxes[(size_t)(n * PRE + i) * 4]);
                float* dst = out + OFF_ROIS + (size_t)(n * POST + k) * 4;
                dst[0] = bx.x; dst[1] = bx.y; dst[2] = bx.z; dst[3] = bx.w;
                k++;
            }
        }
    }
}

// ---------------- launch ----------------
extern "C" void kernel_launch(void* const* d_in, const int* in_sizes, int n_in,
                              void* d_out, int out_size) {
    const float* feat0   = (const float*)d_in[0];
    const float* feat1   = (const float*)d_in[1];
    const float* feat2   = (const float*)d_in[2];
    const float* conv_w  = (const float*)d_in[3];
    const float* conv_b  = (const float*)d_in[4];
    const float* score_w = (const float*)d_in[5];
    const float* score_b = (const float*)d_in[6];
    const float* loc_w   = (const float*)d_in[7];
    const float* loc_b   = (const float*)d_in[8];
    const float* anchors = (const float*)d_in[9];
    float* out = (float*)d_out;

    // conv 3x3: all 3 levels in a single launch (800 + 208 + 56 blocks)
    conv3x3_relu_all<<<1064, 128>>>(feat0, feat1, feat2, conv_w, conv_b);

    // heads: 26250 positions, 8 warps/block
    heads_kernel<<<3282, 256>>>(score_w, score_b, loc_w, loc_b, out);

    // proposals + sort keys (2 x 65536)
    propose_kernel<<<512, 256>>>(anchors, out);

    // bitonic sort ascending per 65536 segment
    bitonic_shared_a<<<64, 1024>>>();
    for (int k = 4096; k <= 65536; k <<= 1) {
        for (int j = k >> 1; j >= 2048; j >>= 1)
            bitonic_global<<<256, 256>>>(j, k);
        bitonic_shared_b<<<64, 1024>>>(k);
    }

    // top-2000 gather, NMS mask, finalize
    gather_topk<<<16, 256>>>();
    nms_mask<<<dim3(250, 2), 256>>>();
    nms_finalize<<<2, 256>>>(out);

    // anchors passthrough
    cudaMemcpyAsync(out + OFF_ANCH, anchors, (size_t)A_TOTAL * 4 * sizeof(float),
                    cudaMemcpyDeviceToDevice, 0);
}